// round 3
// baseline (speedup 1.0000x reference)
#include <cuda_runtime.h>
#include <cstdint>
#include <math.h>

#define L 256
#define D 128
#define H 4
#define DH 32
#define NROW (L * L)

// ---------------- scratch (device globals; no allocations allowed) ----------
__device__ float g_x[NROW * D];      // LayerNorm output
__device__ float g_q[NROW * D];      // q (pre-scaled)
__device__ float g_k[NROW * D];
__device__ float g_v[NROW * D];
__device__ float g_gate[NROW * D];   // sigmoid(x Wg + bg)
__device__ float g_bias[H * NROW];   // biasT[h][j*L + k]
__device__ float g_gout[NROW * D];   // gate * attn_out

__device__ __forceinline__ float to_tf32(float x) {
    unsigned int u;
    asm("cvt.rna.tf32.f32 %0, %1;" : "=r"(u) : "f"(x));
    return __uint_as_float(u);
}

// ---------------- LayerNorm: one warp per row of 128 -----------------------
__global__ __launch_bounds__(256) void ln_kernel(const float* __restrict__ pair,
                                                 const float* __restrict__ ln_w,
                                                 const float* __restrict__ ln_b) {
    int t = threadIdx.x;
    int lane = t & 31;
    int warp = t >> 5;
    int n = blockIdx.x * 8 + warp;  // row
    const float4 xv = *(const float4*)&pair[(size_t)n * D + lane * 4];
    float s  = xv.x + xv.y + xv.z + xv.w;
    float s2 = xv.x * xv.x + xv.y * xv.y + xv.z * xv.z + xv.w * xv.w;
#pragma unroll
    for (int off = 16; off > 0; off >>= 1) {
        s  += __shfl_xor_sync(0xffffffffu, s,  off);
        s2 += __shfl_xor_sync(0xffffffffu, s2, off);
    }
    float mean = s * (1.0f / 128.0f);
    float var  = s2 * (1.0f / 128.0f) - mean * mean;
    float rstd = rsqrtf(var + 1e-5f);
    float4 w4 = *(const float4*)&ln_w[lane * 4];
    float4 b4 = *(const float4*)&ln_b[lane * 4];
    float4 o;
    o.x = (xv.x - mean) * rstd * w4.x + b4.x;
    o.y = (xv.y - mean) * rstd * w4.y + b4.y;
    o.z = (xv.z - mean) * rstd * w4.z + b4.z;
    o.w = (xv.w - mean) * rstd * w4.w + b4.w;
    *(float4*)&g_x[(size_t)n * D + lane * 4] = o;
}

// ---------------- tf32 tensor-core GEMM: [65536,128] @ [128,128] ------------
// Block: 256 threads = 8 warps as 4(M) x 2(N); block tile 128x128, warp 32x64.
// Shared memory holds tiles pre-permuted into mma.sync fragment order so the
// consumer needs only vector LDS (no ldmatrix; b32 ldmatrix doesn't exist).
// mma.sync.m16n8k8 tf32 fragment maps (g = lane>>2, t = lane&3):
//   A: a0=(g,t) a1=(g+8,t) a2=(g,t+4) a3=(g+8,t+4)   -> reg = (m>=8) + 2*(k>=4)
//   B: b0=(k=t,n=g) b1=(k=t+4,n=g)                   -> reg = (k>=4)
//   C: c0=(g,2t) c1=(g,2t+1) c2=(g+8,2t) c3=(g+8,2t+1)
// mode: 0 none, 1 scale by DH^-0.5, 2 sigmoid(acc+bias[col]), 3 acc+bias[col]
__global__ __launch_bounds__(256) void gemm_tf32_kernel(const float* __restrict__ X,
                                                        const float* __restrict__ W,
                                                        float* __restrict__ out,
                                                        int mode,
                                                        const float* __restrict__ bias) {
    __shared__ float As[8][4][128];   // [m-tile][k-step][fragment: lane*4+reg]
    __shared__ float Bs[4][16][64];   // [k-step][n-tile][fragment: lane*2+reg]

    int t = threadIdx.x;
    int lane = t & 31;
    int warp = t >> 5;
    int warp_m = warp >> 1;           // 0..3
    int warp_n = warp & 1;            // 0..1
    int m0 = blockIdx.x * 128;

    float acc[2][8][4];
#pragma unroll
    for (int wm = 0; wm < 2; wm++)
#pragma unroll
        for (int nt = 0; nt < 8; nt++)
#pragma unroll
            for (int r = 0; r < 4; r++) acc[wm][nt][r] = 0.0f;

    for (int k0 = 0; k0 < D; k0 += 32) {
        // ---- producer: X tile 128x32 -> fragment-permuted As -------------
#pragma unroll
        for (int it = 0; it < 4; it++) {
            int f4 = t + it * 256;        // 0..1023
            int m  = f4 >> 3;             // 0..127
            int c4 = f4 & 7;              // k' = c4*4 + j
            float4 v = *(const float4*)&X[(size_t)(m0 + m) * D + k0 + c4 * 4];
            int mt = m >> 4;
            int mr = m & 15;
            int ks = c4 >> 1;
            int regk = (c4 & 1) * 2;      // k>=4 within 8-wide step
            int mhalf = (mr >> 3) & 1;
            float* tb = &As[mt][ks][0];
            float vals[4] = {v.x, v.y, v.z, v.w};
#pragma unroll
            for (int j = 0; j < 4; j++)
                tb[((mr & 7) * 4 + j) * 4 + mhalf + regk] = to_tf32(vals[j]);
        }
        // ---- producer: W tile 32x128 -> fragment-permuted Bs -------------
#pragma unroll
        for (int it = 0; it < 4; it++) {
            int f4 = t + it * 256;
            int r  = f4 >> 5;             // k' 0..31
            int c4 = f4 & 31;             // n' = c4*4 + j
            float4 v = *(const float4*)&W[(size_t)(k0 + r) * 128 + c4 * 4];
            int ks = r >> 3;
            int kk = r & 7;
            int nt = c4 >> 1;
            int nbase = (c4 & 1) * 4;
            int regb = (kk >= 4) ? 1 : 0;
            int k4 = kk & 3;
            float* tb = &Bs[ks][nt][0];
            float vals[4] = {v.x, v.y, v.z, v.w};
#pragma unroll
            for (int j = 0; j < 4; j++)
                tb[((nbase + j) * 4 + k4) * 2 + regb] = to_tf32(vals[j]);
        }
        __syncthreads();

#pragma unroll
        for (int ks = 0; ks < 4; ks++) {
            uint4 afr[2];
#pragma unroll
            for (int wm = 0; wm < 2; wm++)
                afr[wm] = *(const uint4*)&As[warp_m * 2 + wm][ks][lane * 4];
            uint2 bfr[8];
#pragma unroll
            for (int nt = 0; nt < 8; nt++)
                bfr[nt] = *(const uint2*)&Bs[ks][warp_n * 8 + nt][lane * 2];
#pragma unroll
            for (int wm = 0; wm < 2; wm++)
#pragma unroll
                for (int nt = 0; nt < 8; nt++) {
                    asm volatile(
                        "mma.sync.aligned.m16n8k8.row.col.f32.tf32.tf32.f32 "
                        "{%0,%1,%2,%3}, {%4,%5,%6,%7}, {%8,%9}, {%0,%1,%2,%3};"
                        : "+f"(acc[wm][nt][0]), "+f"(acc[wm][nt][1]),
                          "+f"(acc[wm][nt][2]), "+f"(acc[wm][nt][3])
                        : "r"(afr[wm].x), "r"(afr[wm].y), "r"(afr[wm].z), "r"(afr[wm].w),
                          "r"(bfr[nt].x), "r"(bfr[nt].y));
                }
        }
        __syncthreads();
    }

    // ---- epilogue ----------------------------------------------------------
    const float qscale = 0.17677669529663687f;  // 32^-0.5
    int g  = lane >> 2;
    int tid = lane & 3;
#pragma unroll
    for (int wm = 0; wm < 2; wm++) {
        int row0 = m0 + warp_m * 32 + wm * 16 + g;
#pragma unroll
        for (int nt = 0; nt < 8; nt++) {
            int col = warp_n * 64 + nt * 8 + tid * 2;
            float b0 = 0.f, b1 = 0.f;
            if (mode >= 2) { b0 = bias[col]; b1 = bias[col + 1]; }
            float v[4];
#pragma unroll
            for (int r = 0; r < 4; r++) {
                float a = acc[wm][nt][r];
                float bb = (r & 1) ? b1 : b0;
                if (mode == 1)      a *= qscale;
                else if (mode == 2) a = 1.0f / (1.0f + __expf(-(a + bb)));
                else if (mode == 3) a += bb;
                v[r] = a;
            }
            *(float2*)&out[(size_t)row0 * 128 + col]        = make_float2(v[0], v[1]);
            *(float2*)&out[(size_t)(row0 + 8) * 128 + col]  = make_float2(v[2], v[3]);
        }
    }
}

// ---------------- bias projection: biasT[h][n] = x[n] . Wb[:,h] ------------
__global__ __launch_bounds__(256) void bias_kernel(const float* __restrict__ Wb) {
    int t = threadIdx.x;
    int lane = t & 31;
    int warp = t >> 5;
    int n = blockIdx.x * 8 + warp;
    float4 xv = *(const float4*)&g_x[(size_t)n * D + lane * 4];
    float xs[4] = {xv.x, xv.y, xv.z, xv.w};
    float p0 = 0.f, p1 = 0.f, p2 = 0.f, p3 = 0.f;
#pragma unroll
    for (int q = 0; q < 4; q++) {
        float4 wb = *(const float4*)&Wb[(lane * 4 + q) * H];
        p0 += xs[q] * wb.x;
        p1 += xs[q] * wb.y;
        p2 += xs[q] * wb.z;
        p3 += xs[q] * wb.w;
    }
#pragma unroll
    for (int off = 16; off > 0; off >>= 1) {
        p0 += __shfl_xor_sync(0xffffffffu, p0, off);
        p1 += __shfl_xor_sync(0xffffffffu, p1, off);
        p2 += __shfl_xor_sync(0xffffffffu, p2, off);
        p3 += __shfl_xor_sync(0xffffffffu, p3, off);
    }
    if (lane == 0) {
        g_bias[0 * NROW + n] = p0;
        g_bias[1 * NROW + n] = p1;
        g_bias[2 * NROW + n] = p2;
        g_bias[3 * NROW + n] = p3;
    }
}

// ---------------- attention: block = (i, h); thread = j --------------------
__global__ __launch_bounds__(256) void attn_kernel() {
    extern __shared__ float sh[];
    float* Ks = sh;                 // [256][32]
    float* Vs = sh + L * DH;        // [256][32]

    int i = blockIdx.x;
    int h = blockIdx.y;
    int j = threadIdx.x;

    const float* kbase = g_k + (size_t)i * L * D + h * DH;
    const float* vbase = g_v + (size_t)i * L * D + h * DH;
#pragma unroll
    for (int it = 0; it < 8; it++) {
        int f4 = j + it * 256;
        int kk = f4 >> 3;
        int d4 = f4 & 7;
        *(float4*)&Ks[kk * DH + d4 * 4] = *(const float4*)&kbase[(size_t)kk * D + d4 * 4];
        *(float4*)&Vs[kk * DH + d4 * 4] = *(const float4*)&vbase[(size_t)kk * D + d4 * 4];
    }

    float4 q4[8];
    const float* qbase = g_q + ((size_t)i * L + j) * D + h * DH;
#pragma unroll
    for (int d4 = 0; d4 < 8; d4++) q4[d4] = *(const float4*)&qbase[d4 * 4];

    __syncthreads();

    const float* brow = g_bias + (size_t)h * NROW + (size_t)j * L;
    float lsum = 0.0f;
    float4 o4[8];
#pragma unroll
    for (int d4 = 0; d4 < 8; d4++) { o4[d4].x = 0.f; o4[d4].y = 0.f; o4[d4].z = 0.f; o4[d4].w = 0.f; }

    for (int k4 = 0; k4 < L / 4; k4++) {
        float4 b4 = *(const float4*)&brow[k4 * 4];
        float bv[4] = {b4.x, b4.y, b4.z, b4.w};
#pragma unroll
        for (int u = 0; u < 4; u++) {
            int kk = k4 * 4 + u;
            const float4* kr = (const float4*)&Ks[kk * DH];
            float s = bv[u];
#pragma unroll
            for (int d4 = 0; d4 < 8; d4++) {
                float4 kv = kr[d4];
                s += q4[d4].x * kv.x + q4[d4].y * kv.y + q4[d4].z * kv.z + q4[d4].w * kv.w;
            }
            float p = __expf(s);
            lsum += p;
            const float4* vr = (const float4*)&Vs[kk * DH];
#pragma unroll
            for (int d4 = 0; d4 < 8; d4++) {
                float4 vv = vr[d4];
                o4[d4].x += p * vv.x;
                o4[d4].y += p * vv.y;
                o4[d4].z += p * vv.z;
                o4[d4].w += p * vv.w;
            }
        }
    }

    float inv = 1.0f / lsum;
    const float* gbase = g_gate + ((size_t)i * L + j) * D + h * DH;
    float* obase = g_gout + ((size_t)i * L + j) * D + h * DH;
#pragma unroll
    for (int d4 = 0; d4 < 8; d4++) {
        float4 g = *(const float4*)&gbase[d4 * 4];
        float4 r;
        r.x = o4[d4].x * inv * g.x;
        r.y = o4[d4].y * inv * g.y;
        r.z = o4[d4].z * inv * g.z;
        r.w = o4[d4].w * inv * g.w;
        *(float4*)&obase[d4 * 4] = r;
    }
}

// ---------------- launch ----------------------------------------------------
extern "C" void kernel_launch(void* const* d_in, const int* in_sizes, int n_in,
                              void* d_out, int out_size) {
    const float* pair = (const float*)d_in[0];
    const float* ln_w = (const float*)d_in[1];
    const float* ln_b = (const float*)d_in[2];
    const float* Wq   = (const float*)d_in[3];
    const float* Wk   = (const float*)d_in[4];
    const float* Wv   = (const float*)d_in[5];
    const float* Wb   = (const float*)d_in[6];
    const float* Wg   = (const float*)d_in[7];
    const float* bg   = (const float*)d_in[8];
    const float* Wo   = (const float*)d_in[9];
    const float* bo   = (const float*)d_in[10];
    float* out = (float*)d_out;

    float *px, *pq, *pk, *pv, *pgate, *pgout;
    cudaGetSymbolAddress((void**)&px,    g_x);
    cudaGetSymbolAddress((void**)&pq,    g_q);
    cudaGetSymbolAddress((void**)&pk,    g_k);
    cudaGetSymbolAddress((void**)&pv,    g_v);
    cudaGetSymbolAddress((void**)&pgate, g_gate);
    cudaGetSymbolAddress((void**)&pgout, g_gout);

    cudaFuncSetAttribute(attn_kernel, cudaFuncAttributeMaxDynamicSharedMemorySize,
                         2 * L * DH * (int)sizeof(float));

    ln_kernel<<<NROW / 8, 256>>>(pair, ln_w, ln_b);

    gemm_tf32_kernel<<<NROW / 128, 256>>>(px, Wq, pq, 1, nullptr);
    gemm_tf32_kernel<<<NROW / 128, 256>>>(px, Wk, pk, 0, nullptr);
    gemm_tf32_kernel<<<NROW / 128, 256>>>(px, Wv, pv, 0, nullptr);
    gemm_tf32_kernel<<<NROW / 128, 256>>>(px, Wg, pgate, 2, bg);
    bias_kernel<<<NROW / 8, 256>>>(Wb);

    attn_kernel<<<dim3(L, H), 256, 2 * L * DH * sizeof(float)>>>();

    gemm_tf32_kernel<<<NROW / 128, 256>>>(pgout, Wo, out, 3, bo);
}

// round 5
// speedup vs baseline: 1.2810x; 1.2810x over previous
#include <cuda_runtime.h>
#include <cstdint>
#include <math.h>

#define L 256
#define D 128
#define H 4
#define DH 32
#define NROW (L * L)

// ---------------- scratch (device globals; no allocations allowed) ----------
__device__ float g_x[NROW * D];      // LayerNorm output (fp32, row-major)
__device__ float g_xp[NROW * D];     // x in tf32 mma A-fragment order
__device__ float g_q[NROW * D];
__device__ float g_k[NROW * D];
__device__ float g_v[NROW * D];
__device__ float g_gate[NROW * D];
__device__ float g_bias[H * NROW];   // biasT[h][j*L + k]
__device__ float g_gout[NROW * D];   // gate * attn_out (fp32, row-major)
__device__ float g_goutp[NROW * D];  // gout in A-fragment order
__device__ float g_wp[5 * 16 * 1024];// 5 weights in B-fragment order (tf32)

__device__ __forceinline__ float to_tf32(float x) {
    unsigned int u;
    asm("cvt.rna.tf32.f32 %0, %1;" : "=r"(u) : "f"(x));
    return __uint_as_float(u);
}

// ---------------- LayerNorm: one warp per row of 128 -----------------------
__global__ __launch_bounds__(256) void ln_kernel(const float* __restrict__ pair,
                                                 const float* __restrict__ ln_w,
                                                 const float* __restrict__ ln_b) {
    int t = threadIdx.x;
    int lane = t & 31;
    int warp = t >> 5;
    int n = blockIdx.x * 8 + warp;
    const float4 xv = *(const float4*)&pair[(size_t)n * D + lane * 4];
    float s  = xv.x + xv.y + xv.z + xv.w;
    float s2 = xv.x * xv.x + xv.y * xv.y + xv.z * xv.z + xv.w * xv.w;
#pragma unroll
    for (int off = 16; off > 0; off >>= 1) {
        s  += __shfl_xor_sync(0xffffffffu, s,  off);
        s2 += __shfl_xor_sync(0xffffffffu, s2, off);
    }
    float mean = s * (1.0f / 128.0f);
    float var  = s2 * (1.0f / 128.0f) - mean * mean;
    float rstd = rsqrtf(var + 1e-5f);
    float4 w4 = *(const float4*)&ln_w[lane * 4];
    float4 b4 = *(const float4*)&ln_b[lane * 4];
    float4 o;
    o.x = (xv.x - mean) * rstd * w4.x + b4.x;
    o.y = (xv.y - mean) * rstd * w4.y + b4.y;
    o.z = (xv.z - mean) * rstd * w4.z + b4.z;
    o.w = (xv.w - mean) * rstd * w4.w + b4.w;
    *(float4*)&g_x[(size_t)n * D + lane * 4] = o;
}

// ---------------- A-operand permute: row-major -> mma fragment order --------
// Block = one 16-row m-tile. dst[tile*2048 + ks*128 + lane*4 + reg], where for
// element (mr, kk): lane = (mr&7)*4 + (kk&3), reg = (mr>>3) + 2*((kk>>2)&1).
__global__ __launch_bounds__(256) void permute_a_kernel(const float* __restrict__ src,
                                                        float* __restrict__ dst) {
    __shared__ float s[16][132];
    int t = threadIdx.x;
    size_t base = (size_t)blockIdx.x * (16 * 128);
#pragma unroll
    for (int it = 0; it < 2; it++) {
        int f4 = t + it * 256;
        int row = f4 >> 5;
        int c4 = f4 & 31;
        float4 v = *(const float4*)&src[base + row * 128 + c4 * 4];
        s[row][c4 * 4 + 0] = v.x;
        s[row][c4 * 4 + 1] = v.y;
        s[row][c4 * 4 + 2] = v.z;
        s[row][c4 * 4 + 3] = v.w;
    }
    __syncthreads();
    int lane = t & 31;
    int w = t >> 5;
    int g  = lane >> 2;
    int tt = lane & 3;
#pragma unroll
    for (int q = 0; q < 2; q++) {
        int ks = w * 2 + q;          // 0..15 k-steps of 8
        float4 o;
        o.x = to_tf32(s[g][ks * 8 + tt]);
        o.y = to_tf32(s[g + 8][ks * 8 + tt]);
        o.z = to_tf32(s[g][ks * 8 + tt + 4]);
        o.w = to_tf32(s[g + 8][ks * 8 + tt + 4]);
        *(float4*)&dst[base + ks * 128 + lane * 4] = o;
    }
}

// ---------------- W permute: [128][128] row-major -> B-fragment order -------
// dst[ks*1024 + nt*64 + lane*2 + reg]: lane = (n&7)*4 + (kk&3), reg = (kk>>2)&1
__global__ __launch_bounds__(256) void permute_w_kernel(const float* __restrict__ Wq,
                                                        const float* __restrict__ Wk,
                                                        const float* __restrict__ Wv,
                                                        const float* __restrict__ Wg,
                                                        const float* __restrict__ Wo) {
    const float* srcs[5] = {Wq, Wk, Wv, Wg, Wo};
    const float* W = srcs[blockIdx.x];
    float* dst = g_wp + blockIdx.x * 16384;
    for (int i = threadIdx.x; i < 16384; i += 256) {
        int kk = i >> 7;
        int n  = i & 127;
        int ks = kk >> 3;
        int nt = n >> 3;
        int lane = (n & 7) * 4 + (kk & 3);
        int reg  = (kk >> 2) & 1;
        dst[ks * 1024 + nt * 64 + lane * 2 + reg] = to_tf32(W[i]);
    }
}

// ---------------- tf32 GEMM from pre-permuted operands ----------------------
// Block tile 128x128, 8 warps = 4(M) x 2(N); warp = 32 rows x 64 cols.
// Hot loop: coalesced LDG.128 -> STS.128 staging, conflict-free LDS, mma.
// mode: 0 none, 1 q-scale, 2 sigmoid(acc+bias[col]), 3 acc+bias[col]
__global__ __launch_bounds__(256) void gemm_tf32_kernel(const float* __restrict__ Xp,
                                                        int wsel,
                                                        float* __restrict__ out,
                                                        int mode,
                                                        const float* __restrict__ bias) {
    __shared__ float As[8][512];    // 8 m-tiles x (4 ks * 128 fragment floats)
    __shared__ float Bs[4096];      // 4 ks x 16 nt x 64 fragment floats

    int t = threadIdx.x;
    int lane = t & 31;
    int warp = t >> 5;
    int warp_m = warp >> 1;
    int warp_n = warp & 1;
    size_t mtb = (size_t)blockIdx.x * 8;
    const float* wp = g_wp + (size_t)wsel * 16384;

    float acc[2][8][4];
#pragma unroll
    for (int wm = 0; wm < 2; wm++)
#pragma unroll
        for (int nt = 0; nt < 8; nt++)
#pragma unroll
            for (int r = 0; r < 4; r++) acc[wm][nt][r] = 0.0f;

    for (int k0s = 0; k0s < 4; k0s++) {
        // stage A: 8 m-tiles x 4 ks x 128 floats = 4096 floats = 1024 float4
#pragma unroll
        for (int it = 0; it < 4; it++) {
            int f4 = t + it * 256;       // 0..1023
            int mt  = f4 >> 7;           // 0..7
            int off = f4 & 127;          // float4 index within 512-float chunk
            float4 v = *(const float4*)&Xp[((mtb + mt) * 16 + k0s * 4) * 128 + off * 4];
            *(float4*)&As[mt][off * 4] = v;
        }
        // stage B: 4 ks x 1024 floats = 4096 floats = 1024 float4
#pragma unroll
        for (int it = 0; it < 4; it++) {
            int f4 = t + it * 256;
            float4 v = *(const float4*)&wp[k0s * 4096 + f4 * 4];
            *(float4*)&Bs[f4 * 4] = v;
        }
        __syncthreads();

#pragma unroll
        for (int ks = 0; ks < 4; ks++) {
            uint4 afr[2];
            afr[0] = *(const uint4*)&As[warp_m * 2 + 0][ks * 128 + lane * 4];
            afr[1] = *(const uint4*)&As[warp_m * 2 + 1][ks * 128 + lane * 4];
            uint2 bfr[8];
#pragma unroll
            for (int nt = 0; nt < 8; nt++)
                bfr[nt] = *(const uint2*)&Bs[ks * 1024 + (warp_n * 8 + nt) * 64 + lane * 2];
#pragma unroll
            for (int wm = 0; wm < 2; wm++)
#pragma unroll
                for (int nt = 0; nt < 8; nt++) {
                    asm volatile(
                        "mma.sync.aligned.m16n8k8.row.col.f32.tf32.tf32.f32 "
                        "{%0,%1,%2,%3}, {%4,%5,%6,%7}, {%8,%9}, {%0,%1,%2,%3};"
                        : "+f"(acc[wm][nt][0]), "+f"(acc[wm][nt][1]),
                          "+f"(acc[wm][nt][2]), "+f"(acc[wm][nt][3])
                        : "r"(afr[wm].x), "r"(afr[wm].y), "r"(afr[wm].z), "r"(afr[wm].w),
                          "r"(bfr[nt].x), "r"(bfr[nt].y));
                }
        }
        __syncthreads();
    }

    // ---- epilogue (same as validated R3) -----------------------------------
    const float qscale = 0.17677669529663687f;  // 32^-0.5
    int g   = lane >> 2;
    int tid = lane & 3;
    int m0 = blockIdx.x * 128;
#pragma unroll
    for (int wm = 0; wm < 2; wm++) {
        int row0 = m0 + warp_m * 32 + wm * 16 + g;
#pragma unroll
        for (int nt = 0; nt < 8; nt++) {
            int col = warp_n * 64 + nt * 8 + tid * 2;
            float b0 = 0.f, b1 = 0.f;
            if (mode >= 2) { b0 = bias[col]; b1 = bias[col + 1]; }
            float v[4];
#pragma unroll
            for (int r = 0; r < 4; r++) {
                float a = acc[wm][nt][r];
                float bb = (r & 1) ? b1 : b0;
                if (mode == 1)      a *= qscale;
                else if (mode == 2) a = 1.0f / (1.0f + __expf(-(a + bb)));
                else if (mode == 3) a += bb;
                v[r] = a;
            }
            *(float2*)&out[(size_t)row0 * 128 + col]       = make_float2(v[0], v[1]);
            *(float2*)&out[(size_t)(row0 + 8) * 128 + col] = make_float2(v[2], v[3]);
        }
    }
}

// ---------------- bias projection: biasT[h][n] = x[n] . Wb[:,h] ------------
__global__ __launch_bounds__(256) void bias_kernel(const float* __restrict__ Wb) {
    int t = threadIdx.x;
    int lane = t & 31;
    int warp = t >> 5;
    int n = blockIdx.x * 8 + warp;
    float4 xv = *(const float4*)&g_x[(size_t)n * D + lane * 4];
    float xs[4] = {xv.x, xv.y, xv.z, xv.w};
    float p0 = 0.f, p1 = 0.f, p2 = 0.f, p3 = 0.f;
#pragma unroll
    for (int q = 0; q < 4; q++) {
        float4 wb = *(const float4*)&Wb[(lane * 4 + q) * H];
        p0 += xs[q] * wb.x;
        p1 += xs[q] * wb.y;
        p2 += xs[q] * wb.z;
        p3 += xs[q] * wb.w;
    }
#pragma unroll
    for (int off = 16; off > 0; off >>= 1) {
        p0 += __shfl_xor_sync(0xffffffffu, p0, off);
        p1 += __shfl_xor_sync(0xffffffffu, p1, off);
        p2 += __shfl_xor_sync(0xffffffffu, p2, off);
        p3 += __shfl_xor_sync(0xffffffffu, p3, off);
    }
    if (lane == 0) {
        g_bias[0 * NROW + n] = p0;
        g_bias[1 * NROW + n] = p1;
        g_bias[2 * NROW + n] = p2;
        g_bias[3 * NROW + n] = p3;
    }
}

// ---------------- attention: block = (i, h); thread = j --------------------
__global__ __launch_bounds__(256) void attn_kernel() {
    extern __shared__ float sh[];
    float* Ks = sh;                 // [256][32]
    float* Vs = sh + L * DH;        // [256][32]

    int i = blockIdx.x;
    int h = blockIdx.y;
    int j = threadIdx.x;

    const float* kbase = g_k + (size_t)i * L * D + h * DH;
    const float* vbase = g_v + (size_t)i * L * D + h * DH;
#pragma unroll
    for (int it = 0; it < 8; it++) {
        int f4 = j + it * 256;
        int kk = f4 >> 3;
        int d4 = f4 & 7;
        *(float4*)&Ks[kk * DH + d4 * 4] = *(const float4*)&kbase[(size_t)kk * D + d4 * 4];
        *(float4*)&Vs[kk * DH + d4 * 4] = *(const float4*)&vbase[(size_t)kk * D + d4 * 4];
    }

    float4 q4[8];
    const float* qbase = g_q + ((size_t)i * L + j) * D + h * DH;
#pragma unroll
    for (int d4 = 0; d4 < 8; d4++) q4[d4] = *(const float4*)&qbase[d4 * 4];

    __syncthreads();

    const float* brow = g_bias + (size_t)h * NROW + (size_t)j * L;
    float lsum = 0.0f;
    float4 o4[8];
#pragma unroll
    for (int d4 = 0; d4 < 8; d4++) { o4[d4].x = 0.f; o4[d4].y = 0.f; o4[d4].z = 0.f; o4[d4].w = 0.f; }

    for (int k4 = 0; k4 < L / 4; k4++) {
        float4 b4 = *(const float4*)&brow[k4 * 4];
        float bv[4] = {b4.x, b4.y, b4.z, b4.w};
#pragma unroll
        for (int u = 0; u < 4; u++) {
            int kk = k4 * 4 + u;
            const float4* kr = (const float4*)&Ks[kk * DH];
            float s = bv[u];
#pragma unroll
            for (int d4 = 0; d4 < 8; d4++) {
                float4 kv = kr[d4];
                s += q4[d4].x * kv.x + q4[d4].y * kv.y + q4[d4].z * kv.z + q4[d4].w * kv.w;
            }
            float p = __expf(s);
            lsum += p;
            const float4* vr = (const float4*)&Vs[kk * DH];
#pragma unroll
            for (int d4 = 0; d4 < 8; d4++) {
                float4 vv = vr[d4];
                o4[d4].x += p * vv.x;
                o4[d4].y += p * vv.y;
                o4[d4].z += p * vv.z;
                o4[d4].w += p * vv.w;
            }
        }
    }

    float inv = 1.0f / lsum;
    const float* gbase = g_gate + ((size_t)i * L + j) * D + h * DH;
    float* obase = g_gout + ((size_t)i * L + j) * D + h * DH;
#pragma unroll
    for (int d4 = 0; d4 < 8; d4++) {
        float4 g = *(const float4*)&gbase[d4 * 4];
        float4 r;
        r.x = o4[d4].x * inv * g.x;
        r.y = o4[d4].y * inv * g.y;
        r.z = o4[d4].z * inv * g.z;
        r.w = o4[d4].w * inv * g.w;
        *(float4*)&obase[d4 * 4] = r;
    }
}

// ---------------- launch ----------------------------------------------------
extern "C" void kernel_launch(void* const* d_in, const int* in_sizes, int n_in,
                              void* d_out, int out_size) {
    const float* pair = (const float*)d_in[0];
    const float* ln_w = (const float*)d_in[1];
    const float* ln_b = (const float*)d_in[2];
    const float* Wq   = (const float*)d_in[3];
    const float* Wk   = (const float*)d_in[4];
    const float* Wv   = (const float*)d_in[5];
    const float* Wb   = (const float*)d_in[6];
    const float* Wg   = (const float*)d_in[7];
    const float* bg   = (const float*)d_in[8];
    const float* Wo   = (const float*)d_in[9];
    const float* bo   = (const float*)d_in[10];
    float* out = (float*)d_out;

    float *px, *pxp, *pq, *pk, *pv, *pgate, *pgout, *pgoutp;
    cudaGetSymbolAddress((void**)&px,     g_x);
    cudaGetSymbolAddress((void**)&pxp,    g_xp);
    cudaGetSymbolAddress((void**)&pq,     g_q);
    cudaGetSymbolAddress((void**)&pk,     g_k);
    cudaGetSymbolAddress((void**)&pv,     g_v);
    cudaGetSymbolAddress((void**)&pgate,  g_gate);
    cudaGetSymbolAddress((void**)&pgout,  g_gout);
    cudaGetSymbolAddress((void**)&pgoutp, g_goutp);

    cudaFuncSetAttribute(attn_kernel, cudaFuncAttributeMaxDynamicSharedMemorySize,
                         2 * L * DH * (int)sizeof(float));

    ln_kernel<<<NROW / 8, 256>>>(pair, ln_w, ln_b);
    permute_w_kernel<<<5, 256>>>(Wq, Wk, Wv, Wg, Wo);
    permute_a_kernel<<<NROW / 16, 256>>>(px, pxp);

    gemm_tf32_kernel<<<NROW / 128, 256>>>(pxp, 0, pq, 1, nullptr);
    gemm_tf32_kernel<<<NROW / 128, 256>>>(pxp, 1, pk, 0, nullptr);
    gemm_tf32_kernel<<<NROW / 128, 256>>>(pxp, 2, pv, 0, nullptr);
    gemm_tf32_kernel<<<NROW / 128, 256>>>(pxp, 3, pgate, 2, bg);
    bias_kernel<<<NROW / 8, 256>>>(Wb);

    attn_kernel<<<dim3(L, H), 256, 2 * L * DH * sizeof(float)>>>();

    permute_a_kernel<<<NROW / 16, 256>>>(pgout, pgoutp);
    gemm_tf32_kernel<<<NROW / 128, 256>>>(pgoutp, 4, out, 3, bo);
}

// round 6
// speedup vs baseline: 1.6409x; 1.2810x over previous
#include <cuda_runtime.h>
#include <cstdint>
#include <math.h>

#define L 256
#define D 128
#define H 4
#define DH 32
#define NROW (L * L)
#define LOG2E 1.4426950408889634f

// ---------------- scratch (device globals; no allocations allowed) ----------
__device__ float g_x[NROW * D];      // LayerNorm output (fp32, row-major)
__device__ float g_xp[NROW * D];     // x in tf32 mma A-fragment order
__device__ float g_q[NROW * D];      // q (scaled by DH^-0.5 * log2e)
__device__ float g_k[NROW * D];
__device__ float g_v[NROW * D];
__device__ float g_qp[NROW * D];     // per-(i,h) A-frag Q
__device__ float g_kp[NROW * D];     // per-(i,h) B-frag K^T
__device__ float g_vp[NROW * D];     // per-(i,h) B-frag V
__device__ float g_gate[NROW * D];
__device__ float g_bias[H * NROW];   // biasT[h][j*L + k]  (pre-multiplied by log2e)
__device__ float g_gout[NROW * D];   // gate * attn_out (fp32, row-major)
__device__ float g_goutp[NROW * D];  // gout in A-fragment order
__device__ float g_wp[5 * 16 * 1024];// 5 weights in B-fragment order (tf32)

__device__ __forceinline__ float to_tf32(float x) {
    unsigned int u;
    asm("cvt.rna.tf32.f32 %0, %1;" : "=r"(u) : "f"(x));
    return __uint_as_float(u);
}
__device__ __forceinline__ float fast_ex2(float x) {
    float y;
    asm("ex2.approx.ftz.f32 %0, %1;" : "=f"(y) : "f"(x));
    return y;
}

// ---------------- LayerNorm ---------------------------------------------
__global__ __launch_bounds__(256) void ln_kernel(const float* __restrict__ pair,
                                                 const float* __restrict__ ln_w,
                                                 const float* __restrict__ ln_b) {
    int t = threadIdx.x;
    int lane = t & 31;
    int warp = t >> 5;
    int n = blockIdx.x * 8 + warp;
    const float4 xv = *(const float4*)&pair[(size_t)n * D + lane * 4];
    float s  = xv.x + xv.y + xv.z + xv.w;
    float s2 = xv.x * xv.x + xv.y * xv.y + xv.z * xv.z + xv.w * xv.w;
#pragma unroll
    for (int off = 16; off > 0; off >>= 1) {
        s  += __shfl_xor_sync(0xffffffffu, s,  off);
        s2 += __shfl_xor_sync(0xffffffffu, s2, off);
    }
    float mean = s * (1.0f / 128.0f);
    float var  = s2 * (1.0f / 128.0f) - mean * mean;
    float rstd = rsqrtf(var + 1e-5f);
    float4 w4 = *(const float4*)&ln_w[lane * 4];
    float4 b4 = *(const float4*)&ln_b[lane * 4];
    float4 o;
    o.x = (xv.x - mean) * rstd * w4.x + b4.x;
    o.y = (xv.y - mean) * rstd * w4.y + b4.y;
    o.z = (xv.z - mean) * rstd * w4.z + b4.z;
    o.w = (xv.w - mean) * rstd * w4.w + b4.w;
    *(float4*)&g_x[(size_t)n * D + lane * 4] = o;
}

// ---------------- A-operand permute (16-row tiles, D=128) -------------------
__global__ __launch_bounds__(256) void permute_a_kernel(const float* __restrict__ src,
                                                        float* __restrict__ dst) {
    __shared__ float s[16][132];
    int t = threadIdx.x;
    size_t base = (size_t)blockIdx.x * (16 * 128);
#pragma unroll
    for (int it = 0; it < 2; it++) {
        int f4 = t + it * 256;
        int row = f4 >> 5;
        int c4 = f4 & 31;
        float4 v = *(const float4*)&src[base + row * 128 + c4 * 4];
        s[row][c4 * 4 + 0] = v.x;
        s[row][c4 * 4 + 1] = v.y;
        s[row][c4 * 4 + 2] = v.z;
        s[row][c4 * 4 + 3] = v.w;
    }
    __syncthreads();
    int lane = t & 31;
    int w = t >> 5;
    int g  = lane >> 2;
    int tt = lane & 3;
#pragma unroll
    for (int q = 0; q < 2; q++) {
        int ks = w * 2 + q;
        float4 o;
        o.x = to_tf32(s[g][ks * 8 + tt]);
        o.y = to_tf32(s[g + 8][ks * 8 + tt]);
        o.z = to_tf32(s[g][ks * 8 + tt + 4]);
        o.w = to_tf32(s[g + 8][ks * 8 + tt + 4]);
        *(float4*)&dst[base + ks * 128 + lane * 4] = o;
    }
}

// ---------------- W permute -------------------------------------------------
__global__ __launch_bounds__(256) void permute_w_kernel(const float* __restrict__ Wq,
                                                        const float* __restrict__ Wk,
                                                        const float* __restrict__ Wv,
                                                        const float* __restrict__ Wg,
                                                        const float* __restrict__ Wo) {
    const float* srcs[5] = {Wq, Wk, Wv, Wg, Wo};
    const float* W = srcs[blockIdx.x];
    float* dst = g_wp + blockIdx.x * 16384;
    for (int i = threadIdx.x; i < 16384; i += 256) {
        int kk = i >> 7;
        int n  = i & 127;
        int ks = kk >> 3;
        int nt = n >> 3;
        int lane = (n & 7) * 4 + (kk & 3);
        int reg  = (kk >> 2) & 1;
        dst[ks * 1024 + nt * 64 + lane * 2 + reg] = to_tf32(W[i]);
    }
}

// ---------------- tf32 GEMM from pre-permuted operands ----------------------
__global__ __launch_bounds__(256) void gemm_tf32_kernel(const float* __restrict__ Xp,
                                                        int wsel,
                                                        float* __restrict__ out,
                                                        int mode,
                                                        const float* __restrict__ bias) {
    __shared__ float As[8][512];
    __shared__ float Bs[4096];

    int t = threadIdx.x;
    int lane = t & 31;
    int warp = t >> 5;
    int warp_m = warp >> 1;
    int warp_n = warp & 1;
    size_t mtb = (size_t)blockIdx.x * 8;
    const float* wp = g_wp + (size_t)wsel * 16384;

    float acc[2][8][4];
#pragma unroll
    for (int wm = 0; wm < 2; wm++)
#pragma unroll
        for (int nt = 0; nt < 8; nt++)
#pragma unroll
            for (int r = 0; r < 4; r++) acc[wm][nt][r] = 0.0f;

    for (int k0s = 0; k0s < 4; k0s++) {
#pragma unroll
        for (int it = 0; it < 4; it++) {
            int f4 = t + it * 256;
            int mt  = f4 >> 7;
            int off = f4 & 127;
            float4 v = *(const float4*)&Xp[((mtb + mt) * 16 + k0s * 4) * 128 + off * 4];
            *(float4*)&As[mt][off * 4] = v;
        }
#pragma unroll
        for (int it = 0; it < 4; it++) {
            int f4 = t + it * 256;
            float4 v = *(const float4*)&wp[k0s * 4096 + f4 * 4];
            *(float4*)&Bs[f4 * 4] = v;
        }
        __syncthreads();

#pragma unroll
        for (int ks = 0; ks < 4; ks++) {
            uint4 afr[2];
            afr[0] = *(const uint4*)&As[warp_m * 2 + 0][ks * 128 + lane * 4];
            afr[1] = *(const uint4*)&As[warp_m * 2 + 1][ks * 128 + lane * 4];
            uint2 bfr[8];
#pragma unroll
            for (int nt = 0; nt < 8; nt++)
                bfr[nt] = *(const uint2*)&Bs[ks * 1024 + (warp_n * 8 + nt) * 64 + lane * 2];
#pragma unroll
            for (int wm = 0; wm < 2; wm++)
#pragma unroll
                for (int nt = 0; nt < 8; nt++) {
                    asm volatile(
                        "mma.sync.aligned.m16n8k8.row.col.f32.tf32.tf32.f32 "
                        "{%0,%1,%2,%3}, {%4,%5,%6,%7}, {%8,%9}, {%0,%1,%2,%3};"
                        : "+f"(acc[wm][nt][0]), "+f"(acc[wm][nt][1]),
                          "+f"(acc[wm][nt][2]), "+f"(acc[wm][nt][3])
                        : "r"(afr[wm].x), "r"(afr[wm].y), "r"(afr[wm].z), "r"(afr[wm].w),
                          "r"(bfr[nt].x), "r"(bfr[nt].y));
                }
        }
        __syncthreads();
    }

    // q-scale folds in log2e so attention can use exp2 directly
    const float qscale = 0.17677669529663687f * LOG2E;
    int g   = lane >> 2;
    int tid = lane & 3;
    int m0 = blockIdx.x * 128;
#pragma unroll
    for (int wm = 0; wm < 2; wm++) {
        int row0 = m0 + warp_m * 32 + wm * 16 + g;
#pragma unroll
        for (int nt = 0; nt < 8; nt++) {
            int col = warp_n * 64 + nt * 8 + tid * 2;
            float b0 = 0.f, b1 = 0.f;
            if (mode >= 2) { b0 = bias[col]; b1 = bias[col + 1]; }
            float v[4];
#pragma unroll
            for (int r = 0; r < 4; r++) {
                float a = acc[wm][nt][r];
                float bb = (r & 1) ? b1 : b0;
                if (mode == 1)      a *= qscale;
                else if (mode == 2) a = 1.0f / (1.0f + __expf(-(a + bb)));
                else if (mode == 3) a += bb;
                v[r] = a;
            }
            *(float2*)&out[(size_t)row0 * 128 + col]       = make_float2(v[0], v[1]);
            *(float2*)&out[(size_t)(row0 + 8) * 128 + col] = make_float2(v[2], v[3]);
        }
    }
}

// ---------------- bias projection (pre-multiplied by log2e) ----------------
__global__ __launch_bounds__(256) void bias_kernel(const float* __restrict__ Wb) {
    int t = threadIdx.x;
    int lane = t & 31;
    int warp = t >> 5;
    int n = blockIdx.x * 8 + warp;
    float4 xv = *(const float4*)&g_x[(size_t)n * D + lane * 4];
    float xs[4] = {xv.x, xv.y, xv.z, xv.w};
    float p0 = 0.f, p1 = 0.f, p2 = 0.f, p3 = 0.f;
#pragma unroll
    for (int q = 0; q < 4; q++) {
        float4 wb = *(const float4*)&Wb[(lane * 4 + q) * H];
        p0 += xs[q] * wb.x;
        p1 += xs[q] * wb.y;
        p2 += xs[q] * wb.z;
        p3 += xs[q] * wb.w;
    }
#pragma unroll
    for (int off = 16; off > 0; off >>= 1) {
        p0 += __shfl_xor_sync(0xffffffffu, p0, off);
        p1 += __shfl_xor_sync(0xffffffffu, p1, off);
        p2 += __shfl_xor_sync(0xffffffffu, p2, off);
        p3 += __shfl_xor_sync(0xffffffffu, p3, off);
    }
    if (lane == 0) {
        g_bias[0 * NROW + n] = p0 * LOG2E;
        g_bias[1 * NROW + n] = p1 * LOG2E;
        g_bias[2 * NROW + n] = p2 * LOG2E;
        g_bias[3 * NROW + n] = p3 * LOG2E;
    }
}

// ---------------- attention operand permute: block = (i, h) ----------------
// Produces per-(i,h) 8192-float fragment buffers:
//  qp: A-frag [mt16][ks4][128]; kp: B-frag of K^T [nt32][ks4][64];
//  vp: B-frag of V [ksk32][ntd4][64].
__global__ __launch_bounds__(256) void attn_permute_kernel() {
    __shared__ float s[256][33];
    int t = threadIdx.x;
    int i = blockIdx.x;
    int h = blockIdx.y;
    size_t src_off = ((size_t)i * 256) * 128 + h * 32;
    size_t base = ((size_t)(i * 4 + h)) * 8192;

    const float* srcs[3];
    {
        // phase 0: q, 1: k, 2: v
    }
    const float* sq = g_q + src_off;
    const float* sk = g_k + src_off;
    const float* sv = g_v + src_off;

#pragma unroll 1
    for (int phase = 0; phase < 3; phase++) {
        const float* src = (phase == 0) ? sq : (phase == 1) ? sk : sv;
        float* dst = (phase == 0) ? (g_qp + base) : (phase == 1) ? (g_kp + base) : (g_vp + base);
        // load 256x32 slice
#pragma unroll
        for (int it = 0; it < 8; it++) {
            int f4 = t + it * 256;
            int r  = f4 >> 3;
            int c4 = f4 & 7;
            float4 v = *(const float4*)&src[(size_t)r * 128 + c4 * 4];
            s[r][c4 * 4 + 0] = v.x;
            s[r][c4 * 4 + 1] = v.y;
            s[r][c4 * 4 + 2] = v.z;
            s[r][c4 * 4 + 3] = v.w;
        }
        __syncthreads();
        if (phase == 0) {
#pragma unroll
            for (int it = 0; it < 32; it++) {
                int idx = it * 256 + t;
                int mt   = idx >> 9;
                int ks   = (idx >> 7) & 3;
                int lane = (idx >> 2) & 31;
                int reg  = idx & 3;
                int j = mt * 16 + (reg & 1) * 8 + (lane >> 2);
                int d = ks * 8 + (reg >> 1) * 4 + (lane & 3);
                dst[idx] = to_tf32(s[j][d]);
            }
        } else if (phase == 1) {
#pragma unroll
            for (int it = 0; it < 32; it++) {
                int idx = it * 256 + t;
                int nt   = idx >> 8;
                int ks   = (idx >> 6) & 3;
                int lane = (idx >> 1) & 31;
                int reg  = idx & 1;
                int key = nt * 8 + (lane >> 2);
                int d   = ks * 8 + reg * 4 + (lane & 3);
                dst[idx] = to_tf32(s[key][d]);
            }
        } else {
#pragma unroll
            for (int it = 0; it < 32; it++) {
                int idx = it * 256 + t;
                int ksk  = idx >> 8;
                int ntd  = (idx >> 6) & 3;
                int lane = (idx >> 1) & 31;
                int reg  = idx & 1;
                int key = ksk * 8 + reg * 4 + (lane & 3);
                int d   = ntd * 8 + (lane >> 2);
                dst[idx] = to_tf32(s[key][d]);
            }
        }
        __syncthreads();
    }
}

// ---------------- tensor-core attention -------------------------------------
// grid (i=256, jt=2, h=4); 8 warps; warp handles 16 j-rows.
__global__ __launch_bounds__(256) void attn_mma_kernel() {
    __shared__ float Pbuf[8][512];    // per-warp exp(S) tile in A-frag order

    int t = threadIdx.x;
    int lane = t & 31;
    int warp = t >> 5;
    int g  = lane >> 2;
    int tq = lane & 3;
    int i  = blockIdx.x;
    int jt = blockIdx.y;
    int h  = blockIdx.z;

    size_t base = ((size_t)(i * 4 + h)) * 8192;
    const float* qp = g_qp + base;
    const float* kp = g_kp + base;
    const float* vp = g_vp + base;

    int mt_global = jt * 8 + warp;
    int j0 = mt_global * 16;

    uint4 qf[4];
#pragma unroll
    for (int ks = 0; ks < 4; ks++)
        qf[ks] = *(const uint4*)&qp[mt_global * 512 + ks * 128 + lane * 4];

    const float* brow0 = g_bias + (size_t)h * NROW + (size_t)(j0 + g) * 256;
    const float* brow1 = brow0 + 8 * 256;

    float lsum0 = 0.f, lsum1 = 0.f;
    float oacc[4][4];
#pragma unroll
    for (int nt = 0; nt < 4; nt++)
#pragma unroll
        for (int r = 0; r < 4; r++) oacc[nt][r] = 0.f;

    float* pb = &Pbuf[warp][0];
    int e0 = (2 * tq) & 3;
    int e1 = (2 * tq + 1) & 3;
    int rb = 2 * (tq >> 1);

    for (int c = 0; c < 8; c++) {
#pragma unroll
        for (int nt = 0; nt < 4; nt++) {
            float sacc[4] = {0.f, 0.f, 0.f, 0.f};
#pragma unroll
            for (int ks = 0; ks < 4; ks++) {
                uint2 bf = *(const uint2*)&kp[(c * 4 + nt) * 256 + ks * 64 + lane * 2];
                asm volatile(
                    "mma.sync.aligned.m16n8k8.row.col.f32.tf32.tf32.f32 "
                    "{%0,%1,%2,%3}, {%4,%5,%6,%7}, {%8,%9}, {%0,%1,%2,%3};"
                    : "+f"(sacc[0]), "+f"(sacc[1]), "+f"(sacc[2]), "+f"(sacc[3])
                    : "r"(qf[ks].x), "r"(qf[ks].y), "r"(qf[ks].z), "r"(qf[ks].w),
                      "r"(bf.x), "r"(bf.y));
            }
            int keyc = c * 32 + nt * 8 + tq * 2;
            float2 b0 = *(const float2*)&brow0[keyc];
            float2 b1 = *(const float2*)&brow1[keyc];
            float p0 = fast_ex2(sacc[0] + b0.x);
            float p1 = fast_ex2(sacc[1] + b0.y);
            float p2 = fast_ex2(sacc[2] + b1.x);
            float p3 = fast_ex2(sacc[3] + b1.y);
            lsum0 += p0 + p1;
            lsum1 += p2 + p3;
            pb[nt * 128 + (g * 4 + e0) * 4 + rb + 0] = p0;
            pb[nt * 128 + (g * 4 + e1) * 4 + rb + 0] = p1;
            pb[nt * 128 + (g * 4 + e0) * 4 + rb + 1] = p2;
            pb[nt * 128 + (g * 4 + e1) * 4 + rb + 1] = p3;
        }
        __syncwarp();
#pragma unroll
        for (int ks = 0; ks < 4; ks++) {
            uint4 pf = *(const uint4*)&pb[ks * 128 + lane * 4];
#pragma unroll
            for (int ntd = 0; ntd < 4; ntd++) {
                uint2 vf = *(const uint2*)&vp[(c * 4 + ks) * 256 + ntd * 64 + lane * 2];
                asm volatile(
                    "mma.sync.aligned.m16n8k8.row.col.f32.tf32.tf32.f32 "
                    "{%0,%1,%2,%3}, {%4,%5,%6,%7}, {%8,%9}, {%0,%1,%2,%3};"
                    : "+f"(oacc[ntd][0]), "+f"(oacc[ntd][1]),
                      "+f"(oacc[ntd][2]), "+f"(oacc[ntd][3])
                    : "r"(pf.x), "r"(pf.y), "r"(pf.z), "r"(pf.w),
                      "r"(vf.x), "r"(vf.y));
            }
        }
        __syncwarp();
    }

    lsum0 += __shfl_xor_sync(0xffffffffu, lsum0, 1);
    lsum0 += __shfl_xor_sync(0xffffffffu, lsum0, 2);
    lsum1 += __shfl_xor_sync(0xffffffffu, lsum1, 1);
    lsum1 += __shfl_xor_sync(0xffffffffu, lsum1, 2);
    float inv0 = 1.0f / lsum0;
    float inv1 = 1.0f / lsum1;

    size_t row0 = (size_t)(i * 256 + j0 + g) * 128 + h * 32;
    size_t row1 = row0 + 8 * 128;
#pragma unroll
    for (int ntd = 0; ntd < 4; ntd++) {
        int col = ntd * 8 + tq * 2;
        float2 g0 = *(const float2*)&g_gate[row0 + col];
        float2 g1 = *(const float2*)&g_gate[row1 + col];
        float2 o0 = make_float2(oacc[ntd][0] * inv0 * g0.x, oacc[ntd][1] * inv0 * g0.y);
        float2 o1 = make_float2(oacc[ntd][2] * inv1 * g1.x, oacc[ntd][3] * inv1 * g1.y);
        *(float2*)&g_gout[row0 + col] = o0;
        *(float2*)&g_gout[row1 + col] = o1;
    }
}

// ---------------- launch ----------------------------------------------------
extern "C" void kernel_launch(void* const* d_in, const int* in_sizes, int n_in,
                              void* d_out, int out_size) {
    const float* pair = (const float*)d_in[0];
    const float* ln_w = (const float*)d_in[1];
    const float* ln_b = (const float*)d_in[2];
    const float* Wq   = (const float*)d_in[3];
    const float* Wk   = (const float*)d_in[4];
    const float* Wv   = (const float*)d_in[5];
    const float* Wb   = (const float*)d_in[6];
    const float* Wg   = (const float*)d_in[7];
    const float* bg   = (const float*)d_in[8];
    const float* Wo   = (const float*)d_in[9];
    const float* bo   = (const float*)d_in[10];
    float* out = (float*)d_out;

    float *px, *pxp, *pq, *pk, *pv, *pgate, *pgout, *pgoutp;
    cudaGetSymbolAddress((void**)&px,     g_x);
    cudaGetSymbolAddress((void**)&pxp,    g_xp);
    cudaGetSymbolAddress((void**)&pq,     g_q);
    cudaGetSymbolAddress((void**)&pk,     g_k);
    cudaGetSymbolAddress((void**)&pv,     g_v);
    cudaGetSymbolAddress((void**)&pgate,  g_gate);
    cudaGetSymbolAddress((void**)&pgout,  g_gout);
    cudaGetSymbolAddress((void**)&pgoutp, g_goutp);

    ln_kernel<<<NROW / 8, 256>>>(pair, ln_w, ln_b);
    permute_w_kernel<<<5, 256>>>(Wq, Wk, Wv, Wg, Wo);
    permute_a_kernel<<<NROW / 16, 256>>>(px, pxp);

    gemm_tf32_kernel<<<NROW / 128, 256>>>(pxp, 0, pq, 1, nullptr);
    gemm_tf32_kernel<<<NROW / 128, 256>>>(pxp, 1, pk, 0, nullptr);
    gemm_tf32_kernel<<<NROW / 128, 256>>>(pxp, 2, pv, 0, nullptr);
    gemm_tf32_kernel<<<NROW / 128, 256>>>(pxp, 3, pgate, 2, bg);
    bias_kernel<<<NROW / 8, 256>>>(Wb);

    attn_permute_kernel<<<dim3(L, H), 256>>>();
    attn_mma_kernel<<<dim3(L, 2, H), 256>>>();

    permute_a_kernel<<<NROW / 16, 256>>>(pgout, pgoutp);
    gemm_tf32_kernel<<<NROW / 128, 256>>>(pgoutp, 4, out, 3, bo);
}